// round 12
// baseline (speedup 1.0000x reference)
#include <cuda_runtime.h>
#include <math.h>
#include <limits.h>

#define B     32
#define D     512
#define M     10000
#define KTOP  5
#define R3    32768
#define EPS   1e-12f

// sim tiling: block = 128 keys x 32 b x 64 d. 256 threads.
#define KPB   128           // keys per block
#define NDQ   8             // D slices of 64 floats = 16 float4
#define NBLK  79            // ceil(10000 / 128)

typedef unsigned long long ull;

// -------- device scratch --------
__device__ float g_spart[NDQ][B * M];   // partial dots per d-slice
__device__ float g_knp[NDQ][M];         // partial key norms^2
__device__ float g_rk[M];
__device__ float g_rq[B];
__device__ int   g_topidx[B * KTOP];
__device__ float g_topval[B * KTOP];

// -------- packed f32x2 helpers --------
__device__ __forceinline__ void fma2(ull& d, ull a, ull b) {
    asm("fma.rn.f32x2 %0, %1, %2, %0;" : "+l"(d) : "l"(a), "l"(b));
}
__device__ __forceinline__ float2 up2(ull v) {
    float2 f;
    asm("mov.b64 {%0, %1}, %2;" : "=f"(f.x), "=f"(f.y) : "l"(v));
    return f;
}

// ============================================================
// Kernel 1: partial similarity. grid = (79, 8), block = 256.
// Warp: 32 keys x 16 b. Thread: 1 key x 16 b (lane = key).
// kv: per-lane LDS.128 (rotated layout, conflict-free).
// xv: warp-uniform LDS.128 (broadcast = 1 crossbar phase).
// Crossbar phases per 32 fma2: 20 (vs 32 in old tile).
// ============================================================
__global__ void __launch_bounds__(256, 4) k_sim(const float* __restrict__ x,
                                                const float* __restrict__ keys) {
    __shared__ float4 ks4[KPB * 16];    // rotated: [k][(col + k) & 15]
    __shared__ float4 xs4[32 * 16];     // plain [b][col]

    const int tid  = threadIdx.x;
    const int lane = tid & 31;
    const int w    = tid >> 5;           // 0..7
    const int kg   = w & 3;              // key group
    const int bh   = w >> 2;             // b half: 0 -> b 0..15, 1 -> 16..31
    const int m0   = blockIdx.x * KPB;
    const int dq   = blockIdx.y;
    const int doff = dq * 16;            // float4 offset into D

    const float4* __restrict__ x4    = (const float4*)x;     // [32][128]
    const float4* __restrict__ keys4 = (const float4*)keys;  // [10000][128]

    // ---- fill keys: 128 rows x 16 f4, rotated store ----
    #pragma unroll
    for (int r = 0; r < 8; ++r) {
        int flat = tid + 256 * r;        // < 2048
        int k    = flat >> 4;
        int col  = flat & 15;
        int gm   = m0 + k;
        float4 v = (gm < M) ? keys4[(size_t)gm * 128 + doff + col]
                            : make_float4(0.f, 0.f, 0.f, 0.f);
        ks4[k * 16 + ((col + k) & 15)] = v;
    }
    // ---- fill x: 32 rows x 16 f4 ----
    #pragma unroll
    for (int r = 0; r < 2; ++r) {
        int flat = tid + 256 * r;        // < 512
        int bb   = flat >> 4;
        int col  = flat & 15;
        xs4[bb * 16 + col] = x4[bb * 128 + doff + col];
    }
    __syncthreads();

    // ---- key norm partials: 2 threads per key ----
    {
        const int kn = tid >> 1;         // 0..127
        const int h  = tid & 1;
        float np = 0.f;
        #pragma unroll
        for (int i = 0; i < 8; ++i) {
            int col = h * 8 + i;
            float4 v = ks4[kn * 16 + ((col + kn) & 15)];
            np += v.x * v.x + v.y * v.y + v.z * v.z + v.w * v.w;
        }
        np += __shfl_xor_sync(0xFFFFFFFFu, np, 1);
        if (h == 0 && m0 + kn < M) g_knp[dq][m0 + kn] = np;
    }

    // ---- compute ----
    const int myk = kg * 32 + lane;      // this thread's key row (local)
    ull acc[16];
    #pragma unroll
    for (int i = 0; i < 16; ++i) acc[i] = 0ull;

    const float4* kp = ks4 + myk * 16;
    const float4* xp = xs4 + bh * 256;   // 16 rows x 16 f4

    #pragma unroll
    for (int d4c = 0; d4c < 16; ++d4c) {
        ulonglong2 kv = *(const ulonglong2*)(kp + ((d4c + myk) & 15));
        #pragma unroll
        for (int bb = 0; bb < 16; ++bb) {
            ulonglong2 xv = *(const ulonglong2*)(xp + bb * 16 + d4c);  // broadcast
            fma2(acc[bb], xv.x, kv.x);
            fma2(acc[bb], xv.y, kv.y);
        }
    }

    // ---- epilogue: coalesced partial-dot writes ----
    const int k = m0 + myk;
    if (k < M) {
        #pragma unroll
        for (int bb = 0; bb < 16; ++bb) {
            float2 p = up2(acc[bb]);
            g_spart[dq][(bh * 16 + bb) * M + k] = p.x + p.y;
        }
    }
}

// ============================================================
// Kernel 2: norms. blocks 0..39 -> rk[m]; 40..43 -> rq[b].
// ============================================================
__global__ void __launch_bounds__(256) k_nrm(const float* __restrict__ x) {
    const int bid = blockIdx.x;
    const int tid = threadIdx.x;
    if (bid < 40) {
        int m = bid * 256 + tid;
        if (m < M) {
            float s = 0.f;
            #pragma unroll
            for (int q = 0; q < NDQ; ++q) s += g_knp[q][m];
            g_rk[m] = 1.0f / fmaxf(sqrtf(s), EPS);
        }
    } else {
        int b    = (bid - 40) * 8 + (tid >> 5);
        int lane = tid & 31;
        float s = 0.f;
        #pragma unroll
        for (int c = 0; c < 4; ++c) {
            float4 v = ((const float4*)x)[b * 128 + lane + 32 * c];
            s += v.x * v.x + v.y * v.y + v.z * v.z + v.w * v.w;
        }
        #pragma unroll
        for (int o = 16; o > 0; o >>= 1) s += __shfl_xor_sync(0xFFFFFFFFu, s, o);
        if (lane == 0) g_rq[b] = 1.0f / fmaxf(sqrtf(s), EPS);
    }
}

// ============================================================
// Kernel 3: top-5, float4-vectorized, sums 8 partials.
// Tie-break: lower index (matches jax.lax.top_k).
// ============================================================
#define INS5(v, m)                                                                 \
    if ((v) > t4) {                                                                \
        if ((v) > t0)      { t4=t3;x4=x3; t3=t2;x3=x2; t2=t1;x2=x1; t1=t0;x1=x0; t0=(v);x0=(m); } \
        else if ((v) > t1) { t4=t3;x4=x3; t3=t2;x3=x2; t2=t1;x2=x1; t1=(v);x1=(m); }              \
        else if ((v) > t2) { t4=t3;x4=x3; t3=t2;x3=x2; t2=(v);x2=(m); }                            \
        else if ((v) > t3) { t4=t3;x4=x3; t3=(v);x3=(m); }                                         \
        else               { t4=(v);x4=(m); }                                                      \
    }

__global__ void __launch_bounds__(256) k_topk() {
    __shared__ float s_cv[40];
    __shared__ int   s_ci[40];

    const int b    = blockIdx.x;
    const int tid  = threadIdx.x;
    const int w    = tid >> 5;
    const int lane = tid & 31;

    const float4* __restrict__ rk4 = (const float4*)g_rk;

    float t0 = -INFINITY, t1 = -INFINITY, t2 = -INFINITY, t3 = -INFINITY, t4 = -INFINITY;
    int   x0 = INT_MAX, x1 = INT_MAX, x2 = INT_MAX, x3 = INT_MAX, x4 = INT_MAX;

    #pragma unroll 2
    for (int it = 0; it < 10; ++it) {
        int m4 = tid + 256 * it;
        if (m4 < 2500) {
            float4 sum = ((const float4*)(g_spart[0] + b * M))[m4];
            #pragma unroll
            for (int q = 1; q < NDQ; ++q) {
                float4 p = ((const float4*)(g_spart[q] + b * M))[m4];
                sum.x += p.x; sum.y += p.y; sum.z += p.z; sum.w += p.w;
            }
            float4 r = rk4[m4];
            int m = 4 * m4;
            INS5(sum.x * r.x, m)
            INS5(sum.y * r.y, m + 1)
            INS5(sum.z * r.z, m + 2)
            INS5(sum.w * r.w, m + 3)
        }
    }

    #pragma unroll
    for (int kk = 0; kk < 5; ++kk) {
        float bv = t0; int bi = x0;
        #pragma unroll
        for (int o = 16; o > 0; o >>= 1) {
            float ov = __shfl_xor_sync(0xFFFFFFFFu, bv, o);
            int   oi = __shfl_xor_sync(0xFFFFFFFFu, bi, o);
            if (ov > bv || (ov == bv && oi < bi)) { bv = ov; bi = oi; }
        }
        if (x0 == bi) { t0=t1;x0=x1; t1=t2;x1=x2; t2=t3;x2=x3; t3=t4;x3=x4; t4=-INFINITY;x4=INT_MAX; }
        if (lane == 0) { s_cv[w * 5 + kk] = bv; s_ci[w * 5 + kk] = bi; }
    }
    __syncthreads();

    if (w == 0) {
        float rq = g_rq[b];
        float va = s_cv[lane];
        int   ia = s_ci[lane];
        float vb = (lane + 32 < 40) ? s_cv[lane + 32] : -INFINITY;
        int   ib = (lane + 32 < 40) ? s_ci[lane + 32] : INT_MAX;
        if (vb > va || (vb == va && ib < ia)) {
            float tv = va; va = vb; vb = tv;
            int   ti = ia; ia = ib; ib = ti;
        }
        #pragma unroll
        for (int kk = 0; kk < 5; ++kk) {
            float bv = va; int bi = ia;
            #pragma unroll
            for (int o = 16; o > 0; o >>= 1) {
                float ov = __shfl_xor_sync(0xFFFFFFFFu, bv, o);
                int   oi = __shfl_xor_sync(0xFFFFFFFFu, bi, o);
                if (ov > bv || (ov == bv && oi < bi)) { bv = ov; bi = oi; }
            }
            if (ia == bi) { va = vb; ia = ib; vb = -INFINITY; ib = INT_MAX; }
            if (lane == 0) { g_topval[b * KTOP + kk] = bv * rq; g_topidx[b * KTOP + kk] = bi; }
        }
    }
}

// ============================================================
// Kernel 4: gather. 640 blocks x 32KB, batched MLP=8 (measured best).
// ============================================================
__global__ void __launch_bounds__(256) k_gather(const float* __restrict__ vals,
                                                float* __restrict__ out,
                                                int out_size) {
    const int pair  = blockIdx.x >> 2;   // 0..159
    const int chunk = blockIdx.x & 3;    // 0..3
    const int t     = threadIdx.x;

    const int idx = g_topidx[pair];
    const float4* __restrict__ src = (const float4*)vals + (size_t)idx  * 8192 + chunk * 2048;
    float4*       __restrict__ dst = (float4*)out        + (size_t)pair * 8192 + chunk * 2048;

    float4 tmp[8];
    #pragma unroll
    for (int i = 0; i < 8; ++i) tmp[i] = __ldcs(src + t + 256 * i);
    #pragma unroll
    for (int i = 0; i < 8; ++i) __stcs(dst + t + 256 * i, tmp[i]);

    if (blockIdx.x == 0) {
        const int total = B * KTOP * R3;   // 5242880
        if (out_size >= total + 2 * B * KTOP && t < B * KTOP) {
            out[total + t]            = (float)g_topidx[t];
            out[total + B * KTOP + t] = g_topval[t];
        }
    }
}

// ============================================================
extern "C" void kernel_launch(void* const* d_in, const int* in_sizes, int n_in,
                              void* d_out, int out_size) {
    const float* x    = (const float*)d_in[0];  // (32, 512)
    const float* keys = (const float*)d_in[1];  // (10000, 512)
    const float* vals = (const float*)d_in[2];  // (10000, 32, 32, 32)

    float* out = (float*)d_out;

    k_sim<<<dim3(NBLK, NDQ), 256>>>(x, keys);   // 632 blocks
    k_nrm<<<44, 256>>>(x);
    k_topk<<<B, 256>>>();
    k_gather<<<B * KTOP * 4, 256>>>(vals, out, out_size);
}

// round 14
// speedup vs baseline: 1.0110x; 1.0110x over previous
#include <cuda_runtime.h>
#include <cuda_bf16.h>
#include <math.h>
#include <limits.h>

#define B     32
#define D     512
#define M     10000
#define KTOP  5
#define R3    32768
#define EPS   1e-12f

#define NDQ   8             // k-slices of 64 floats
#define KPB   256           // keys per sim block
// A smem: [256 rows][72 bf16] per matrix (pad 64->72 for conflict-free frags)
#define AROW_BF 72
#define AROW_BYTES (AROW_BF * 2)          // 144
#define A_BYTES (KPB * AROW_BYTES)        // 36864
#define SIM_SMEM (2 * A_BYTES)            // 73728 (hi, lo)

typedef unsigned int u32;

// -------- device scratch --------
__device__ float g_spart[NDQ][B * M];     // partial dots per k-slice
__device__ float g_rk[M];
__device__ float g_rq[B];
__device__ u32   g_xhi[B * 256];          // x hi bf16 pairs [b][k/2]
__device__ u32   g_xlo[B * 256];          // x lo bf16 pairs
__device__ int   g_topidx[B * KTOP];
__device__ float g_topval[B * KTOP];

// ============================================================
// Kernel 0: x -> bf16 hi/lo pairs (u32 = 2 bf16 along k).
// ============================================================
__global__ void k_xcvt(const float* __restrict__ x) {
    int t = blockIdx.x * 256 + threadIdx.x;      // 4096 float4s
    float4 v = ((const float4*)x)[t];
    __nv_bfloat162 h01 = __floats2bfloat162_rn(v.x, v.y);
    __nv_bfloat162 h23 = __floats2bfloat162_rn(v.z, v.w);
    g_xhi[2 * t]     = *(u32*)&h01;
    g_xhi[2 * t + 1] = *(u32*)&h23;
    __nv_bfloat162 l01 = __floats2bfloat162_rn(v.x - __low2float(h01), v.y - __high2float(h01));
    __nv_bfloat162 l23 = __floats2bfloat162_rn(v.z - __low2float(h23), v.w - __high2float(h23));
    g_xlo[2 * t]     = *(u32*)&l01;
    g_xlo[2 * t + 1] = *(u32*)&l23;
}

// ============================================================
// Kernel 1: norms, warp per row. rows 0..9999 -> rk; 10000..10031 -> rq.
// grid 1254 x 256 (8 warps) = 10032 warps (FIX: was 157 blocks -> only
// 1256 warps, leaving 87% of g_rk uninitialized).
// ============================================================
__global__ void __launch_bounds__(256) k_nrm(const float* __restrict__ x,
                                             const float* __restrict__ keys) {
    const int gw   = blockIdx.x * 8 + (threadIdx.x >> 5);
    const int lane = threadIdx.x & 31;
    const float4* src;
    if (gw < M)            src = (const float4*)keys + (size_t)gw * 128;
    else if (gw < M + B)   src = (const float4*)x + (size_t)(gw - M) * 128;
    else return;

    float s = 0.f;
    #pragma unroll
    for (int j = 0; j < 4; ++j) {
        float4 v = src[lane + 32 * j];
        s += v.x * v.x + v.y * v.y + v.z * v.z + v.w * v.w;
    }
    #pragma unroll
    for (int o = 16; o > 0; o >>= 1) s += __shfl_xor_sync(0xFFFFFFFFu, s, o);
    if (lane == 0) {
        float r = 1.0f / fmaxf(sqrtf(s), EPS);
        if (gw < M) g_rk[gw] = r;
        else        g_rq[gw - M] = r;
    }
}

// ============================================================
// Kernel 2: similarity via mma.sync bf16 (hi/lo split, 3 products).
// grid (40, 8), block 256 (8 warps). Block: 256 keys x 32 b x 64 k.
// Warp w: keys [w*32, w*32+32) x all 32 b. Per warp: 2 m16 x 4 n8.
// A = keys (row-major m x k) in smem hi/lo; B = x from global u32 pairs.
// ============================================================
__global__ void __launch_bounds__(256) k_sim(const float* __restrict__ keys) {
    extern __shared__ char smem[];
    char* Ahi = smem;
    char* Alo = smem + A_BYTES;

    const int tid  = threadIdx.x;
    const int lane = tid & 31;
    const int w    = tid >> 5;          // 0..7
    const int gid  = lane >> 2;         // 0..7
    const int tg   = lane & 3;          // 0..3
    const int m0   = blockIdx.x * KPB;
    const int dq   = blockIdx.y;        // k-slice (64 floats)

    // ---- fill + convert keys: 256 rows x 16 f4 ----
    {
        const float4* __restrict__ k4 = (const float4*)keys;
        const int c4   = tid & 15;       // f4 col 0..15
        const int row0 = tid >> 4;       // 0..15
        #pragma unroll
        for (int i = 0; i < 16; ++i) {
            int r  = row0 + 16 * i;
            int gm = m0 + r;
            float4 v = (gm < M) ? k4[(size_t)gm * 128 + dq * 16 + c4]
                                : make_float4(0.f, 0.f, 0.f, 0.f);
            __nv_bfloat162 h01 = __floats2bfloat162_rn(v.x, v.y);
            __nv_bfloat162 h23 = __floats2bfloat162_rn(v.z, v.w);
            __nv_bfloat162 l01 = __floats2bfloat162_rn(v.x - __low2float(h01),
                                                       v.y - __high2float(h01));
            __nv_bfloat162 l23 = __floats2bfloat162_rn(v.z - __low2float(h23),
                                                       v.w - __high2float(h23));
            int off = r * AROW_BYTES + c4 * 8;
            *(uint2*)(Ahi + off) = make_uint2(*(u32*)&h01, *(u32*)&h23);
            *(uint2*)(Alo + off) = make_uint2(*(u32*)&l01, *(u32*)&l23);
        }
    }
    __syncthreads();

    // ---- mma mainloop ----
    float acc[2][4][4];
    #pragma unroll
    for (int mt = 0; mt < 2; ++mt)
        #pragma unroll
        for (int jn = 0; jn < 4; ++jn)
            #pragma unroll
            for (int q = 0; q < 4; ++q) acc[mt][jn][q] = 0.f;

    const int wrow = w * 32;
    const u32* __restrict__ xhi = g_xhi;
    const u32* __restrict__ xlo = g_xlo;

    #pragma unroll
    for (int ks = 0; ks < 4; ++ks) {                 // 4 x k16 = 64 floats
        u32 ah[2][4], al[2][4];
        #pragma unroll
        for (int mt = 0; mt < 2; ++mt) {
            int r0 = wrow + mt * 16 + gid;
            int byt = ks * 32 + tg * 4;              // k-offset in bytes
            ah[mt][0] = *(const u32*)(Ahi + r0 * AROW_BYTES + byt);
            ah[mt][1] = *(const u32*)(Ahi + (r0 + 8) * AROW_BYTES + byt);
            ah[mt][2] = *(const u32*)(Ahi + r0 * AROW_BYTES + byt + 16);
            ah[mt][3] = *(const u32*)(Ahi + (r0 + 8) * AROW_BYTES + byt + 16);
            al[mt][0] = *(const u32*)(Alo + r0 * AROW_BYTES + byt);
            al[mt][1] = *(const u32*)(Alo + (r0 + 8) * AROW_BYTES + byt);
            al[mt][2] = *(const u32*)(Alo + r0 * AROW_BYTES + byt + 16);
            al[mt][3] = *(const u32*)(Alo + (r0 + 8) * AROW_BYTES + byt + 16);
        }
        #pragma unroll
        for (int jn = 0; jn < 4; ++jn) {
            int n = jn * 8 + gid;                    // b index
            int ki = dq * 32 + ks * 8 + tg;          // u32 index along k
            u32 bh0 = xhi[n * 256 + ki];
            u32 bh1 = xhi[n * 256 + ki + 4];
            u32 bl0 = xlo[n * 256 + ki];
            u32 bl1 = xlo[n * 256 + ki + 4];
            #pragma unroll
            for (int mt = 0; mt < 2; ++mt) {
                float* d = acc[mt][jn];
                asm volatile(
                    "mma.sync.aligned.m16n8k16.row.col.f32.bf16.bf16.f32 "
                    "{%0,%1,%2,%3}, {%4,%5,%6,%7}, {%8,%9}, {%0,%1,%2,%3};"
                    : "+f"(d[0]), "+f"(d[1]), "+f"(d[2]), "+f"(d[3])
                    : "r"(ah[mt][0]), "r"(ah[mt][1]), "r"(ah[mt][2]), "r"(ah[mt][3]),
                      "r"(bh0), "r"(bh1));
                asm volatile(
                    "mma.sync.aligned.m16n8k16.row.col.f32.bf16.bf16.f32 "
                    "{%0,%1,%2,%3}, {%4,%5,%6,%7}, {%8,%9}, {%0,%1,%2,%3};"
                    : "+f"(d[0]), "+f"(d[1]), "+f"(d[2]), "+f"(d[3])
                    : "r"(ah[mt][0]), "r"(ah[mt][1]), "r"(ah[mt][2]), "r"(ah[mt][3]),
                      "r"(bl0), "r"(bl1));
                asm volatile(
                    "mma.sync.aligned.m16n8k16.row.col.f32.bf16.bf16.f32 "
                    "{%0,%1,%2,%3}, {%4,%5,%6,%7}, {%8,%9}, {%0,%1,%2,%3};"
                    : "+f"(d[0]), "+f"(d[1]), "+f"(d[2]), "+f"(d[3])
                    : "r"(al[mt][0]), "r"(al[mt][1]), "r"(al[mt][2]), "r"(al[mt][3]),
                      "r"(bh0), "r"(bh1));
            }
        }
    }

    // ---- epilogue: D(m, b) -> g_spart[dq][b*M + m] ----
    #pragma unroll
    for (int mt = 0; mt < 2; ++mt) {
        #pragma unroll
        for (int jn = 0; jn < 4; ++jn) {
            int m1 = m0 + wrow + mt * 16 + gid;
            int m2 = m1 + 8;
            int b1 = jn * 8 + 2 * tg;
            if (m1 < M) {
                g_spart[dq][b1 * M + m1]       = acc[mt][jn][0];
                g_spart[dq][(b1 + 1) * M + m1] = acc[mt][jn][1];
            }
            if (m2 < M) {
                g_spart[dq][b1 * M + m2]       = acc[mt][jn][2];
                g_spart[dq][(b1 + 1) * M + m2] = acc[mt][jn][3];
            }
        }
    }
}

// ============================================================
// Kernel 3: top-5, float4-vectorized, sums 8 partials.
// Tie-break: lower index (matches jax.lax.top_k).
// ============================================================
#define INS5(v, m)                                                                 \
    if ((v) > t4) {                                                                \
        if ((v) > t0)      { t4=t3;x4=x3; t3=t2;x3=x2; t2=t1;x2=x1; t1=t0;x1=x0; t0=(v);x0=(m); } \
        else if ((v) > t1) { t4=t3;x4=x3; t3=t2;x3=x2; t2=t1;x2=x1; t1=(v);x1=(m); }              \
        else if ((v) > t2) { t4=t3;x4=x3; t3=t2;x3=x2; t2=(v);x2=(m); }                            \
        else if ((v) > t3) { t4=t3;x4=x3; t3=(v);x3=(m); }                                         \
        else               { t4=(v);x4=(m); }                                                      \
    }

__global__ void __launch_bounds__(256) k_topk() {
    __shared__ float s_cv[40];
    __shared__ int   s_ci[40];

    const int b    = blockIdx.x;
    const int tid  = threadIdx.x;
    const int w    = tid >> 5;
    const int lane = tid & 31;

    const float4* __restrict__ rk4 = (const float4*)g_rk;

    float t0 = -INFINITY, t1 = -INFINITY, t2 = -INFINITY, t3 = -INFINITY, t4 = -INFINITY;
    int   x0 = INT_MAX, x1 = INT_MAX, x2 = INT_MAX, x3 = INT_MAX, x4 = INT_MAX;

    #pragma unroll 2
    for (int it = 0; it < 10; ++it) {
        int m4 = tid + 256 * it;
        if (m4 < 2500) {
            float4 sum = ((const float4*)(g_spart[0] + b * M))[m4];
            #pragma unroll
            for (int q = 1; q < NDQ; ++q) {
                float4 p = ((const float4*)(g_spart[q] + b * M))[m4];
                sum.x += p.x; sum.y += p.y; sum.z += p.z; sum.w += p.w;
            }
            float4 r = rk4[m4];
            int m = 4 * m4;
            INS5(sum.x * r.x, m)
            INS5(sum.y * r.y, m + 1)
            INS5(sum.z * r.z, m + 2)
            INS5(sum.w * r.w, m + 3)
        }
    }

    #pragma unroll
    for (int kk = 0; kk < 5; ++kk) {
        float bv = t0; int bi = x0;
        #pragma unroll
        for (int o = 16; o > 0; o >>= 1) {
            float ov = __shfl_xor_sync(0xFFFFFFFFu, bv, o);
            int   oi = __shfl_xor_sync(0xFFFFFFFFu, bi, o);
            if (ov > bv || (ov == bv && oi < bi)) { bv = ov; bi = oi; }
        }
        if (x0 == bi) { t0=t1;x0=x1; t1=t2;x1=x2; t2=t3;x2=x3; t3=t4;x3=x4; t4=-INFINITY;x4=INT_MAX; }
        if (lane == 0) { s_cv[w * 5 + kk] = bv; s_ci[w * 5 + kk] = bi; }
    }
    __syncthreads();

    if (w == 0) {
        float rq = g_rq[b];
        float va = s_cv[lane];
        int   ia = s_ci[lane];
        float vb = (lane + 32 < 40) ? s_cv[lane + 32] : -INFINITY;
        int   ib = (lane + 32 < 40) ? s_ci[lane + 32] : INT_MAX;
        if (vb > va || (vb == va && ib < ia)) {
            float tv = va; va = vb; vb = tv;
            int   ti = ia; ia = ib; ib = ti;
        }
        #pragma unroll
        for (int kk = 0; kk < 5; ++kk) {
            float bv = va; int bi = ia;
            #pragma unroll
            for (int o = 16; o > 0; o >>= 1) {
                float ov = __shfl_xor_sync(0xFFFFFFFFu, bv, o);
                int   oi = __shfl_xor_sync(0xFFFFFFFFu, bi, o);
                if (ov > bv || (ov == bv && oi < bi)) { bv = ov; bi = oi; }
            }
            if (ia == bi) { va = vb; ia = ib; vb = -INFINITY; ib = INT_MAX; }
            if (lane == 0) { g_topval[b * KTOP + kk] = bv * rq; g_topidx[b * KTOP + kk] = bi; }
        }
    }
}

// ============================================================
// Kernel 4: gather. 640 blocks x 32KB, batched MLP=8 (measured best).
// ============================================================
__global__ void __launch_bounds__(256) k_gather(const float* __restrict__ vals,
                                                float* __restrict__ out,
                                                int out_size) {
    const int pair  = blockIdx.x >> 2;   // 0..159
    const int chunk = blockIdx.x & 3;    // 0..3
    const int t     = threadIdx.x;

    const int idx = g_topidx[pair];
    const float4* __restrict__ src = (const float4*)vals + (size_t)idx  * 8192 + chunk * 2048;
    float4*       __restrict__ dst = (float4*)out        + (size_t)pair * 8192 + chunk * 2048;

    float4 tmp[8];
    #pragma unroll
    for (int i = 0; i < 8; ++i) tmp[i] = __ldcs(src + t + 256 * i);
    #pragma unroll
    for (int i = 0; i < 8; ++i) __stcs(dst + t + 256 * i, tmp[i]);

    if (blockIdx.x == 0) {
        const int total = B * KTOP * R3;   // 5242880
        if (out_size >= total + 2 * B * KTOP && t < B * KTOP) {
            out[total + t]            = (float)g_topidx[t];
            out[total + B * KTOP + t] = g_topval[t];
        }
    }
}

// ============================================================
extern "C" void kernel_launch(void* const* d_in, const int* in_sizes, int n_in,
                              void* d_out, int out_size) {
    const float* x    = (const float*)d_in[0];  // (32, 512)
    const float* keys = (const float*)d_in[1];  // (10000, 512)
    const float* vals = (const float*)d_in[2];  // (10000, 32, 32, 32)

    float* out = (float*)d_out;

    cudaFuncSetAttribute(k_sim, cudaFuncAttributeMaxDynamicSharedMemorySize, SIM_SMEM);

    k_xcvt<<<16, 256>>>(x);
    k_nrm<<<1254, 256>>>(x, keys);               // 10032 warps (FIXED)
    k_sim<<<dim3(40, NDQ), 256, SIM_SMEM>>>(keys);   // 320 blocks
    k_topk<<<B, 256>>>();
    k_gather<<<B * KTOP * 4, 256>>>(vals, out, out_size);
}